// round 1
// baseline (speedup 1.0000x reference)
#include <cuda_runtime.h>
#include <cstdint>

// Problem shape (fixed by reference setup_inputs)
#define BB 8
#define CC 3
#define HH 768
#define WW 768
#define HW (HH * WW)

__device__ __forceinline__ int wrap768(int v) {
    // 768 = 3*256; use generic mod then fix sign
    v %= HH;
    return v + ((v >> 31) & HH);
}

__global__ void splat_push_kernel(const float* __restrict__ x,
                                  const float* __restrict__ phi,
                                  float* __restrict__ out) {
    int gid = blockIdx.x * blockDim.x + threadIdx.x;
    if (gid >= BB * HW) return;

    int b   = gid / HW;
    int rem = gid - b * HW;
    int i   = rem / WW;
    int j   = rem - i * WW;

    const float* phib = phi + (size_t)b * 2 * HW;
    float pi = __ldg(phib + rem);        // displacement along H
    float pj = __ldg(phib + HW + rem);   // displacement along W

    float gi = (float)i + pi;
    float gj = (float)j + pj;
    float i0f = floorf(gi);
    float j0f = floorf(gj);
    float fi = gi - i0f;
    float fj = gj - j0f;

    int i0 = wrap768((int)i0f);
    int j0 = wrap768((int)j0f);
    int i1 = (i0 + 1 == HH) ? 0 : i0 + 1;
    int j1 = (j0 + 1 == WW) ? 0 : j0 + 1;

    float w00 = (1.0f - fi) * (1.0f - fj);
    float w01 = (1.0f - fi) * fj;
    float w10 = fi * (1.0f - fj);
    float w11 = fi * fj;

    int o00 = i0 * WW + j0;
    int o01 = i0 * WW + j1;
    int o10 = i1 * WW + j0;
    int o11 = i1 * WW + j1;

    const float* xb = x   + (size_t)b * CC * HW + rem;
    float*       ob = out + (size_t)b * CC * HW;

#pragma unroll
    for (int c = 0; c < CC; c++) {
        float v = __ldg(xb + (size_t)c * HW);
        float* oc = ob + (size_t)c * HW;
        atomicAdd(oc + o00, v * w00);
        atomicAdd(oc + o01, v * w01);
        atomicAdd(oc + o10, v * w10);
        atomicAdd(oc + o11, v * w11);
    }
}

extern "C" void kernel_launch(void* const* d_in, const int* in_sizes, int n_in,
                              void* d_out, int out_size) {
    const float* x   = (const float*)d_in[0];
    const float* phi = (const float*)d_in[1];
    float* out = (float*)d_out;

    // Output is poisoned before timing; zero it every launch (memset node is
    // graph-capturable).
    cudaMemsetAsync(out, 0, (size_t)out_size * sizeof(float), 0);

    const int total = BB * HW;
    const int threads = 256;
    const int blocks = (total + threads - 1) / threads;
    splat_push_kernel<<<blocks, threads>>>(x, phi, out);
}

// round 2
// speedup vs baseline: 1.5448x; 1.5448x over previous
#include <cuda_runtime.h>
#include <cstdint>

// Shape fixed by reference setup_inputs
#define BB 8
#define CC 3
#define HH 768
#define WW 768
#define HW (HH * WW)

#define TS 64            // source tile (TS x TS)
#define RR 8             // halo radius
#define WIN (TS + 2*RR)  // 80: output window per tile
#define PLANE (WIN*WIN)  // 6400
#define SMEMN (CC*PLANE) // 19200 floats = 76.8 KB
#define NTHREADS 256

__device__ __forceinline__ int wrap768(int v) {
    v %= HH;
    return v + ((v >> 31) & HH);
}

__global__ void splat_tile_kernel(const float* __restrict__ x,
                                  const float* __restrict__ phi,
                                  float* __restrict__ out) {
    extern __shared__ float tile[];  // [3][80][80]

    const int tid = threadIdx.x;
    const int b   = blockIdx.z;
    const int ti0 = blockIdx.y * TS;
    const int tj0 = blockIdx.x * TS;

    // zero the accumulator window
    #pragma unroll
    for (int t = tid; t < SMEMN; t += NTHREADS) tile[t] = 0.0f;
    __syncthreads();

    const float* phib = phi + (size_t)b * 2 * HW;
    const float* xb   = x   + (size_t)b * CC * HW;
    float*       ob   = out + (size_t)b * CC * HW;

    #pragma unroll 4
    for (int k = 0; k < (TS*TS)/NTHREADS; k++) {
        int p  = tid + k * NTHREADS;
        int li = p >> 6;         // p / 64
        int lj = p & 63;         // p % 64
        int gi_ = ti0 + li;
        int gj_ = tj0 + lj;
        int idx = gi_ * WW + gj_;

        float pi = __ldg(phib + idx);
        float pj = __ldg(phib + HW + idx);

        float posi = (float)gi_ + pi;
        float posj = (float)gj_ + pj;
        float i0f = floorf(posi);
        float j0f = floorf(posj);
        float fi = posi - i0f;
        float fj = posj - j0f;
        int di = (int)i0f;
        int dj = (int)j0f;

        float w00 = (1.0f - fi) * (1.0f - fj);
        float w01 = (1.0f - fi) * fj;
        float w10 = fi * (1.0f - fj);
        float w11 = fi * fj;

        float v0 = __ldg(xb + idx);
        float v1 = __ldg(xb + HW + idx);
        float v2 = __ldg(xb + 2*HW + idx);

        int sr = di - (ti0 - RR);
        int sc = dj - (tj0 - RR);

        if ((unsigned)sr < (unsigned)(WIN - 1) && (unsigned)sc < (unsigned)(WIN - 1)) {
            // both corners inside the smem window
            int o00 = sr * WIN + sc;
            float* t0 = tile;
            float* t1 = tile + PLANE;
            float* t2 = tile + 2*PLANE;
            atomicAdd(t0 + o00,          v0 * w00);
            atomicAdd(t0 + o00 + 1,      v0 * w01);
            atomicAdd(t0 + o00 + WIN,    v0 * w10);
            atomicAdd(t0 + o00 + WIN+1,  v0 * w11);
            atomicAdd(t1 + o00,          v1 * w00);
            atomicAdd(t1 + o00 + 1,      v1 * w01);
            atomicAdd(t1 + o00 + WIN,    v1 * w10);
            atomicAdd(t1 + o00 + WIN+1,  v1 * w11);
            atomicAdd(t2 + o00,          v2 * w00);
            atomicAdd(t2 + o00 + 1,      v2 * w01);
            atomicAdd(t2 + o00 + WIN,    v2 * w10);
            atomicAdd(t2 + o00 + WIN+1,  v2 * w11);
        } else {
            // rare far splat: direct global atomics with wrap
            int i0 = wrap768(di);
            int j0 = wrap768(dj);
            int i1 = (i0 + 1 == HH) ? 0 : i0 + 1;
            int j1 = (j0 + 1 == WW) ? 0 : j0 + 1;
            int g00 = i0 * WW + j0, g01 = i0 * WW + j1;
            int g10 = i1 * WW + j0, g11 = i1 * WW + j1;
            atomicAdd(ob + g00, v0 * w00); atomicAdd(ob + g01, v0 * w01);
            atomicAdd(ob + g10, v0 * w10); atomicAdd(ob + g11, v0 * w11);
            atomicAdd(ob + HW + g00, v1 * w00); atomicAdd(ob + HW + g01, v1 * w01);
            atomicAdd(ob + HW + g10, v1 * w10); atomicAdd(ob + HW + g11, v1 * w11);
            atomicAdd(ob + 2*HW + g00, v2 * w00); atomicAdd(ob + 2*HW + g01, v2 * w01);
            atomicAdd(ob + 2*HW + g10, v2 * w10); atomicAdd(ob + 2*HW + g11, v2 * w11);
        }
    }
    __syncthreads();

    // flush window to global with coalesced atomics
    #pragma unroll
    for (int c = 0; c < CC; c++) {
        float* oc = ob + (size_t)c * HW;
        const float* tc = tile + c * PLANE;
        for (int t = tid; t < PLANE; t += NTHREADS) {
            int r  = t / WIN;
            int cc = t - r * WIN;
            int gi = ti0 - RR + r;
            gi += (gi < 0) ? HH : 0;
            gi -= (gi >= HH) ? HH : 0;
            int gj = tj0 - RR + cc;
            gj += (gj < 0) ? WW : 0;
            gj -= (gj >= WW) ? WW : 0;
            atomicAdd(oc + gi * WW + gj, tc[t]);
        }
    }
}

extern "C" void kernel_launch(void* const* d_in, const int* in_sizes, int n_in,
                              void* d_out, int out_size) {
    const float* x   = (const float*)d_in[0];
    const float* phi = (const float*)d_in[1];
    float* out = (float*)d_out;

    cudaFuncSetAttribute(splat_tile_kernel,
                         cudaFuncAttributeMaxDynamicSharedMemorySize,
                         SMEMN * sizeof(float));

    cudaMemsetAsync(out, 0, (size_t)out_size * sizeof(float), 0);

    dim3 grid(WW / TS, HH / TS, BB);   // (12, 12, 8)
    splat_tile_kernel<<<grid, NTHREADS, SMEMN * sizeof(float)>>>(x, phi, out);
}

// round 3
// speedup vs baseline: 1.5508x; 1.0039x over previous
#include <cuda_runtime.h>
#include <cstdint>

// Shape fixed by reference setup_inputs
#define BB 8
#define CC 3
#define HH 768
#define WW 768
#define HW (HH * WW)

#define TS 64            // source tile (TS x TS)
#define RR 8             // halo radius
#define WIN (TS + 2*RR)  // 80: output window per tile
#define PLANE (WIN*WIN)  // 6400
#define SMEMN (CC*PLANE) // 19200 floats = 76.8 KB
#define NTHREADS 256

__device__ __forceinline__ int wrap768(int v) {
    v %= HH;
    return v + ((v >> 31) & HH);
}

__global__ void splat_tile_kernel(const float* __restrict__ x,
                                  const float* __restrict__ phi,
                                  float* __restrict__ out) {
    extern __shared__ float tile[];  // [3][80][80]

    const int tid = threadIdx.x;
    const int b   = blockIdx.z;
    const int ti0 = blockIdx.y * TS;
    const int tj0 = blockIdx.x * TS;

    // zero the accumulator window
    #pragma unroll
    for (int t = tid; t < SMEMN; t += NTHREADS) tile[t] = 0.0f;
    __syncthreads();

    const float* phib = phi + (size_t)b * 2 * HW;
    const float* xb   = x   + (size_t)b * CC * HW;
    float*       ob   = out + (size_t)b * CC * HW;

    #pragma unroll 4
    for (int k = 0; k < (TS*TS)/NTHREADS; k++) {
        int p  = tid + k * NTHREADS;
        int li = p >> 6;         // p / 64
        int lj = p & 63;         // p % 64
        int gi_ = ti0 + li;
        int gj_ = tj0 + lj;
        int idx = gi_ * WW + gj_;

        float pi = __ldg(phib + idx);
        float pj = __ldg(phib + HW + idx);

        float posi = (float)gi_ + pi;
        float posj = (float)gj_ + pj;
        float i0f = floorf(posi);
        float j0f = floorf(posj);
        float fi = posi - i0f;
        float fj = posj - j0f;
        int di = (int)i0f;
        int dj = (int)j0f;

        float w00 = (1.0f - fi) * (1.0f - fj);
        float w01 = (1.0f - fi) * fj;
        float w10 = fi * (1.0f - fj);
        float w11 = fi * fj;

        float v0 = __ldg(xb + idx);
        float v1 = __ldg(xb + HW + idx);
        float v2 = __ldg(xb + 2*HW + idx);

        int sr = di - (ti0 - RR);
        int sc = dj - (tj0 - RR);

        if ((unsigned)sr < (unsigned)(WIN - 1) && (unsigned)sc < (unsigned)(WIN - 1)) {
            // both corners inside the smem window
            int o00 = sr * WIN + sc;
            float* t0 = tile;
            float* t1 = tile + PLANE;
            float* t2 = tile + 2*PLANE;
            atomicAdd(t0 + o00,          v0 * w00);
            atomicAdd(t0 + o00 + 1,      v0 * w01);
            atomicAdd(t0 + o00 + WIN,    v0 * w10);
            atomicAdd(t0 + o00 + WIN+1,  v0 * w11);
            atomicAdd(t1 + o00,          v1 * w00);
            atomicAdd(t1 + o00 + 1,      v1 * w01);
            atomicAdd(t1 + o00 + WIN,    v1 * w10);
            atomicAdd(t1 + o00 + WIN+1,  v1 * w11);
            atomicAdd(t2 + o00,          v2 * w00);
            atomicAdd(t2 + o00 + 1,      v2 * w01);
            atomicAdd(t2 + o00 + WIN,    v2 * w10);
            atomicAdd(t2 + o00 + WIN+1,  v2 * w11);
        } else {
            // rare far splat: direct global atomics with wrap
            int i0 = wrap768(di);
            int j0 = wrap768(dj);
            int i1 = (i0 + 1 == HH) ? 0 : i0 + 1;
            int j1 = (j0 + 1 == WW) ? 0 : j0 + 1;
            int g00 = i0 * WW + j0, g01 = i0 * WW + j1;
            int g10 = i1 * WW + j0, g11 = i1 * WW + j1;
            atomicAdd(ob + g00, v0 * w00); atomicAdd(ob + g01, v0 * w01);
            atomicAdd(ob + g10, v0 * w10); atomicAdd(ob + g11, v0 * w11);
            atomicAdd(ob + HW + g00, v1 * w00); atomicAdd(ob + HW + g01, v1 * w01);
            atomicAdd(ob + HW + g10, v1 * w10); atomicAdd(ob + HW + g11, v1 * w11);
            atomicAdd(ob + 2*HW + g00, v2 * w00); atomicAdd(ob + 2*HW + g01, v2 * w01);
            atomicAdd(ob + 2*HW + g10, v2 * w10); atomicAdd(ob + 2*HW + g11, v2 * w11);
        }
    }
    __syncthreads();

    // flush window to global with coalesced atomics
    #pragma unroll
    for (int c = 0; c < CC; c++) {
        float* oc = ob + (size_t)c * HW;
        const float* tc = tile + c * PLANE;
        for (int t = tid; t < PLANE; t += NTHREADS) {
            int r  = t / WIN;
            int cc = t - r * WIN;
            int gi = ti0 - RR + r;
            gi += (gi < 0) ? HH : 0;
            gi -= (gi >= HH) ? HH : 0;
            int gj = tj0 - RR + cc;
            gj += (gj < 0) ? WW : 0;
            gj -= (gj >= WW) ? WW : 0;
            atomicAdd(oc + gi * WW + gj, tc[t]);
        }
    }
}

extern "C" void kernel_launch(void* const* d_in, const int* in_sizes, int n_in,
                              void* d_out, int out_size) {
    const float* x   = (const float*)d_in[0];
    const float* phi = (const float*)d_in[1];
    float* out = (float*)d_out;

    cudaFuncSetAttribute(splat_tile_kernel,
                         cudaFuncAttributeMaxDynamicSharedMemorySize,
                         SMEMN * sizeof(float));

    cudaMemsetAsync(out, 0, (size_t)out_size * sizeof(float), 0);

    dim3 grid(WW / TS, HH / TS, BB);   // (12, 12, 8)
    splat_tile_kernel<<<grid, NTHREADS, SMEMN * sizeof(float)>>>(x, phi, out);
}